// round 13
// baseline (speedup 1.0000x reference)
#include <cuda_runtime.h>
#include <cuda_fp16.h>
#include <cstdint>

#define D_FEAT    64
#define MAX_NODES 50000
#define MAX_EDGES 800000

// Scratch (__device__ globals — no allocation allowed).
static __device__ __half g_y[(size_t)MAX_NODES * D_FEAT];     // relu(x W + b), fp16
static __device__ __half g_hout[(size_t)MAX_NODES * D_FEAT];  // fp16 accumulator
static __device__ int2   g_edge[MAX_EDGES];                   // packed (src, dst)
static __device__ int    g_is64;                              // edge_index dtype flag

// ---------------------------------------------------------------------------
// Detect index dtype: int64 indices < 2^31 have every odd 32-bit word == 0.
// ---------------------------------------------------------------------------
__global__ void detect_kernel(const int* __restrict__ ei_words) {
    __shared__ int any_nonzero;
    if (threadIdx.x == 0) any_nonzero = 0;
    __syncthreads();
    if (ei_words[2 * threadIdx.x + 1] != 0) atomicOr(&any_nonzero, 1);
    __syncthreads();
    if (threadIdx.x == 0) g_is64 = any_nonzero ? 0 : 1;
}

// ---------------------------------------------------------------------------
// Pack edge_index into int2 AND zero the fp16 accumulator (fused).
// ---------------------------------------------------------------------------
__global__ __launch_bounds__(256) void prep_kernel(const void* __restrict__ ei,
                                                   int E, int n16) {
    int t = blockIdx.x * blockDim.x + threadIdx.x;
    if (t < E) {
        int src, dst;
        if (g_is64) {
            const long long* p = (const long long*)ei;
            src = (int)__ldg(&p[t]);
            dst = (int)__ldg(&p[(size_t)E + t]);
        } else {
            const int* p = (const int*)ei;
            src = __ldg(&p[t]);
            dst = __ldg(&p[(size_t)E + t]);
        }
        g_edge[t] = make_int2(src, dst);
    }
    if (t < n16) ((uint4*)g_hout)[t] = make_uint4(0u, 0u, 0u, 0u);
}

// ---------------------------------------------------------------------------
// Per-node MLP: y = relu(x @ W + b), stored fp16.
// x read straight from global (L1-resident; 16 lanes broadcast per LDG) —
// no sx tile, smem = 16.9KB -> occupancy cap removed, no x-fill phase.
// W pair-major in smem: sWp[k2][2c+parity]; math = fma.rn.f32x2 on
// (even-k, odd-k) partial pairs. Thread owns rows {r0+16j}, cols {c4+16cc}.
// sWp is reused (post-sync) as fp16 staging; stride 68 halves = 136B so every
// row base is 8B-aligned for the uint2 store path (R12's 66 was the trap).
// ---------------------------------------------------------------------------
__global__ __launch_bounds__(256) void mlp_kernel(const float* __restrict__ x,
                                                  const float* __restrict__ W,
                                                  const float* __restrict__ b,
                                                  int n) {
    __shared__ float sWp[32 * 132];   // [k2][2c+par], stride 132 floats

    const int tid  = threadIdx.x;
    const int row0 = blockIdx.x * 64;

    // Fill sWp: W[k][c] -> sWp[k>>1][2c + (k&1)]
#pragma unroll
    for (int i = 0; i < 4; i++) {
        int idx = tid + 256 * i;          // 0..1023 over W's float4s
        int k   = idx >> 4;
        int kk  = idx & 15;
        float4 v = ((const float4*)W)[idx];
        float* dstrow = &sWp[(k >> 1) * 132 + (k & 1)];
        dstrow[2 * (4 * kk + 0)] = v.x;
        dstrow[2 * (4 * kk + 1)] = v.y;
        dstrow[2 * (4 * kk + 2)] = v.z;
        dstrow[2 * (4 * kk + 3)] = v.w;
    }
    __syncthreads();

    const int c4 = tid & 15;   // cols c4 + 16*cc
    const int r0 = tid >> 4;   // rows r0 + 16*j

    // Clamped row indices so loads are always in-bounds (stores are guarded).
    int rr[4];
#pragma unroll
    for (int j = 0; j < 4; j++) {
        int r = row0 + r0 + 16 * j;
        rr[j] = (r < n) ? r : (n - 1);
    }

    unsigned long long acc[4][4];
#pragma unroll
    for (int j = 0; j < 4; j++)
#pragma unroll
        for (int cc = 0; cc < 4; cc++) acc[j][cc] = 0ULL;

#pragma unroll 4
    for (int k4 = 0; k4 < 16; k4++) {
        // x: 4 rows via global LDG.128 (L1 hit; 16 lanes share each address)
        float4 xw[4];
#pragma unroll
        for (int j = 0; j < 4; j++)
            xw[j] = __ldg((const float4*)(x + (size_t)rr[j] * D_FEAT) + k4);

#pragma unroll
        for (int sub = 0; sub < 2; sub++) {
            int k2 = k4 * 2 + sub;
            unsigned long long wp[4];
#pragma unroll
            for (int cc = 0; cc < 4; cc++)
                wp[cc] = *(const unsigned long long*)
                         &sWp[k2 * 132 + 2 * (c4 + 16 * cc)];
#pragma unroll
            for (int j = 0; j < 4; j++) {
                float2 xp2 = sub ? make_float2(xw[j].z, xw[j].w)
                                 : make_float2(xw[j].x, xw[j].y);
                unsigned long long xp = *(const unsigned long long*)&xp2;
#pragma unroll
                for (int cc = 0; cc < 4; cc++)
                    asm("fma.rn.f32x2 %0, %1, %2, %0;"
                        : "+l"(acc[j][cc]) : "l"(xp), "l"(wp[cc]));
            }
        }
    }

    // Fold pairs, bias, relu; stage fp16 in reused smem for coalesced store.
    float bv[4];
#pragma unroll
    for (int cc = 0; cc < 4; cc++) bv[cc] = __ldg(&b[c4 + 16 * cc]);

    __syncthreads();                       // done reading sWp weights
    __half* stage = (__half*)sWp;          // [64][68] halves, 8.7KB (fits 16.9KB)
#pragma unroll
    for (int j = 0; j < 4; j++) {
#pragma unroll
        for (int cc = 0; cc < 4; cc++) {
            unsigned long long a = acc[j][cc];
            float lo = __uint_as_float((unsigned)(a & 0xFFFFFFFFu));
            float hi = __uint_as_float((unsigned)(a >> 32));
            float s  = fmaxf(lo + hi + bv[cc], 0.f);
            stage[(r0 + 16 * j) * 68 + (c4 + 16 * cc)] = __float2half_rn(s);
        }
    }
    __syncthreads();

    // Coalesced fp16 store: 1024 uint2 (64 rows x 16). Row base = r*136B, 8B-aligned.
#pragma unroll
    for (int i = 0; i < 4; i++) {
        int idx = tid + 256 * i;
        int r   = idx >> 4;
        int kk  = idx & 15;
        if (row0 + r < n) {
            uint2 pk = *(const uint2*)&stage[r * 68 + kk * 4];
            ((uint2*)(g_y + (size_t)(row0 + r) * D_FEAT))[kk] = pk;
        }
    }
}

// ---------------------------------------------------------------------------
// Edge scatter: g_hout[dst] += y[src], all fp16.
// 8 lanes/edge (lane q <-> uint4 = 8 halves; warp = 4 rows x 128B coalesced),
// 4 independent edges/thread (MLP=4), red.v4.f16x2 covers 8 feats per op.
// At the measured L2 atomic-op floor (~1.1 cyc/op/slice).
// ---------------------------------------------------------------------------
__global__ __launch_bounds__(256) void scatter_kernel(int E, int EQ) {
    int t = blockIdx.x * blockDim.x + threadIdx.x;
    int e0 = t >> 3;
    if (e0 >= EQ) return;
    int q = t & 7;

    int2 ed[4];
    bool valid[4];
#pragma unroll
    for (int j = 0; j < 4; j++) {
        int e = e0 + j * EQ;
        valid[j] = (e < E);
        ed[j] = valid[j] ? __ldg(&g_edge[e]) : make_int2(0, 0);
    }

    uint4 hv[4];
#pragma unroll
    for (int j = 0; j < 4; j++)
        hv[j] = __ldg((const uint4*)(g_y + (size_t)ed[j].x * D_FEAT) + q);

#pragma unroll
    for (int j = 0; j < 4; j++) {
        if (!valid[j]) continue;
        __half* o = g_hout + (size_t)ed[j].y * D_FEAT + (q << 3);
        asm volatile("red.global.add.noftz.v4.f16x2 [%0], {%1, %2, %3, %4};"
                     :: "l"(o), "r"(hv[j].x), "r"(hv[j].y), "r"(hv[j].z), "r"(hv[j].w)
                     : "memory");
    }
}

// ---------------------------------------------------------------------------
// Convert fp16 accumulator -> fp32 output. One thread per 8 halves.
// ---------------------------------------------------------------------------
__global__ __launch_bounds__(256) void convert_kernel(float* __restrict__ out, int n16) {
    int i = blockIdx.x * blockDim.x + threadIdx.x;
    if (i >= n16) return;
    uint4 h = ((const uint4*)g_hout)[i];
    float2 f0 = __half22float2(*(const __half2*)&h.x);
    float2 f1 = __half22float2(*(const __half2*)&h.y);
    float2 f2 = __half22float2(*(const __half2*)&h.z);
    float2 f3 = __half22float2(*(const __half2*)&h.w);
    float4* o = (float4*)out + (size_t)i * 2;
    o[0] = make_float4(f0.x, f0.y, f1.x, f1.y);
    o[1] = make_float4(f2.x, f2.y, f3.x, f3.y);
}

// ---------------------------------------------------------------------------
// Inputs: x [n*64 f32], edge_index [2*E int32/int64], W [64*64 f32], b [64].
// ---------------------------------------------------------------------------
extern "C" void kernel_launch(void* const* d_in, const int* in_sizes, int n_in,
                              void* d_out, int out_size) {
    const float* x   = (const float*)d_in[0];
    const void*  ei  = d_in[1];
    const float* W   = (const float*)d_in[2];
    const float* b   = (const float*)d_in[3];
    float*       out = (float*)d_out;

    int n = in_sizes[0] / D_FEAT;
    int E = in_sizes[1] / 2;
    int n16 = n * D_FEAT / 8;   // uint4 groups in the fp16 accumulator

    detect_kernel<<<1, 256>>>((const int*)ei);

    int prep_elems = (E > n16) ? E : n16;
    prep_kernel<<<(prep_elems + 255) / 256, 256>>>(ei, E, n16);

    mlp_kernel<<<(n + 63) / 64, 256>>>(x, W, b, n);

    int EQ = (E + 3) / 4;
    long long total = (long long)EQ * 8;
    int grid = (int)((total + 255) / 256);
    scatter_kernel<<<grid, 256>>>(E, EQ);

    convert_kernel<<<(n16 + 255) / 256, 256>>>(out, n16);
}

// round 14
// speedup vs baseline: 1.1404x; 1.1404x over previous
#include <cuda_runtime.h>
#include <cuda_fp16.h>
#include <cstdint>

#define D_FEAT    64
#define MAX_NODES 50000
#define MAX_EDGES 800000

// Scratch (__device__ globals — no allocation allowed).
static __device__ __half g_y[(size_t)MAX_NODES * D_FEAT];     // relu(x W + b), fp16
static __device__ __half g_hout[(size_t)MAX_NODES * D_FEAT];  // fp16 accumulator
static __device__ int    g_is64;                              // edge_index dtype flag

// ---------------------------------------------------------------------------
// Setup: block 0 detects index dtype (int64 indices < 2^31 have every odd
// 32-bit word == 0); all blocks zero the fp16 accumulator.
// ---------------------------------------------------------------------------
__global__ __launch_bounds__(256) void setup_kernel(const int* __restrict__ ei_words,
                                                    int n16) {
    if (blockIdx.x == 0) {
        __shared__ int any_nonzero;
        if (threadIdx.x == 0) any_nonzero = 0;
        __syncthreads();
        if (ei_words[2 * threadIdx.x + 1] != 0) atomicOr(&any_nonzero, 1);
        __syncthreads();
        if (threadIdx.x == 0) g_is64 = any_nonzero ? 0 : 1;
    }
    int t = blockIdx.x * blockDim.x + threadIdx.x;
    if (t < n16) ((uint4*)g_hout)[t] = make_uint4(0u, 0u, 0u, 0u);
}

// ---------------------------------------------------------------------------
// Per-node MLP: y = relu(x @ W + b), stored fp16.  (R11-proven version.)
// W pair-major in smem (sWp[k2][2c+parity]) + padded x tile; math is
// fma.rn.f32x2 on (even-k, odd-k) partial pairs.
// Thread owns rows {r0+16j}, cols {c4+16cc}.
// ---------------------------------------------------------------------------
__global__ __launch_bounds__(256) void mlp_kernel(const float* __restrict__ x,
                                                  const float* __restrict__ W,
                                                  const float* __restrict__ b,
                                                  int n) {
    __shared__ float sWp[32 * 128];   // [k2][2c+par], 16KB
    __shared__ float sx[64 * 68];     // [r][k], padded stride, 17KB

    const int tid  = threadIdx.x;
    const int row0 = blockIdx.x * 64;

    // Fill sWp: W[k][c] -> sWp[k>>1][2c + (k&1)]
#pragma unroll
    for (int i = 0; i < 4; i++) {
        int idx = tid + 256 * i;          // 0..1023 over W's float4s
        int k   = idx >> 4;
        int kk  = idx & 15;
        float4 v = ((const float4*)W)[idx];
        float* dstrow = &sWp[(k >> 1) * 128 + (k & 1)];
        dstrow[2 * (4 * kk + 0)] = v.x;
        dstrow[2 * (4 * kk + 1)] = v.y;
        dstrow[2 * (4 * kk + 2)] = v.z;
        dstrow[2 * (4 * kk + 3)] = v.w;
    }
    // Fill sx
#pragma unroll
    for (int i = 0; i < 4; i++) {
        int idx = tid + 256 * i;
        int r   = idx >> 4;
        int kk  = idx & 15;
        float4 v = make_float4(0.f, 0.f, 0.f, 0.f);
        if (row0 + r < n)
            v = ((const float4*)(x + (size_t)(row0 + r) * D_FEAT))[kk];
        *(float4*)&sx[r * 68 + kk * 4] = v;
    }
    __syncthreads();

    const int c4 = tid & 15;   // cols c4 + 16*cc
    const int r0 = tid >> 4;   // rows r0 + 16*j

    unsigned long long acc[4][4];
#pragma unroll
    for (int j = 0; j < 4; j++)
#pragma unroll
        for (int cc = 0; cc < 4; cc++) acc[j][cc] = 0ULL;

#pragma unroll 4
    for (int k4 = 0; k4 < 16; k4++) {
        // x: 4 rows, each LDS.128 = two f32x2 pairs
        ulonglong2 xr[4];
#pragma unroll
        for (int j = 0; j < 4; j++)
            xr[j] = *(const ulonglong2*)&sx[(r0 + 16 * j) * 68 + k4 * 4];

#pragma unroll
        for (int sub = 0; sub < 2; sub++) {
            int k2 = k4 * 2 + sub;
            unsigned long long wp[4];
#pragma unroll
            for (int cc = 0; cc < 4; cc++)
                wp[cc] = *(const unsigned long long*)
                         &sWp[k2 * 128 + 2 * (c4 + 16 * cc)];
#pragma unroll
            for (int j = 0; j < 4; j++) {
                unsigned long long xp = sub ? xr[j].y : xr[j].x;
#pragma unroll
                for (int cc = 0; cc < 4; cc++)
                    asm("fma.rn.f32x2 %0, %1, %2, %0;"
                        : "+l"(acc[j][cc]) : "l"(xp), "l"(wp[cc]));
            }
        }
    }

    // Fold pairs, add bias, relu; stage fp32 results into sx (16B-aligned rows).
    float bv[4];
#pragma unroll
    for (int cc = 0; cc < 4; cc++) bv[cc] = __ldg(&b[c4 + 16 * cc]);

    __syncthreads();   // done reading sx; reuse as staging
#pragma unroll
    for (int j = 0; j < 4; j++) {
#pragma unroll
        for (int cc = 0; cc < 4; cc++) {
            unsigned long long a = acc[j][cc];
            float lo = __uint_as_float((unsigned)(a & 0xFFFFFFFFu));
            float hi = __uint_as_float((unsigned)(a >> 32));
            float s  = fmaxf(lo + hi + bv[cc], 0.f);
            sx[(r0 + 16 * j) * 68 + (c4 + 16 * cc)] = s;
        }
    }
    __syncthreads();

    // Coalesced fp16 store.
#pragma unroll
    for (int i = 0; i < 4; i++) {
        int idx = tid + 256 * i;
        int r   = idx >> 4;
        int kk  = idx & 15;
        if (row0 + r < n) {
            float4 v = *(const float4*)&sx[r * 68 + kk * 4];
            __half2 h0 = __floats2half2_rn(v.x, v.y);
            __half2 h1 = __floats2half2_rn(v.z, v.w);
            uint2 pk;
            pk.x = *(const unsigned*)&h0;
            pk.y = *(const unsigned*)&h1;
            ((uint2*)(g_y + (size_t)(row0 + r) * D_FEAT))[kk] = pk;
        }
    }
}

// ---------------------------------------------------------------------------
// Edge scatter: g_hout[dst] += y[src], all fp16, indices read directly from
// edge_index (uniform dtype branch; 8 lanes broadcast each index load).
// 8 lanes/edge (lane q <-> uint4 = 8 halves; warp = 4 rows x 128B coalesced),
// 4 independent edges/thread (MLP=4), red.v4.f16x2 covers 8 feats per op.
// At the measured L2 atomic-op floor.
// ---------------------------------------------------------------------------
__global__ __launch_bounds__(256) void scatter_kernel(const void* __restrict__ ei,
                                                      int E, int EQ) {
    int t = blockIdx.x * blockDim.x + threadIdx.x;
    int e0 = t >> 3;
    if (e0 >= EQ) return;
    int q = t & 7;

    int e[4];
    bool valid[4];
#pragma unroll
    for (int j = 0; j < 4; j++) {
        e[j] = e0 + j * EQ;
        valid[j] = (e[j] < E);
        if (!valid[j]) e[j] = 0;
    }

    int src[4], dst[4];
    if (g_is64) {
        const long long* p = (const long long*)ei;
#pragma unroll
        for (int j = 0; j < 4; j++) src[j] = (int)__ldg(&p[e[j]]);
#pragma unroll
        for (int j = 0; j < 4; j++) dst[j] = (int)__ldg(&p[(size_t)E + e[j]]);
    } else {
        const int* p = (const int*)ei;
#pragma unroll
        for (int j = 0; j < 4; j++) src[j] = __ldg(&p[e[j]]);
#pragma unroll
        for (int j = 0; j < 4; j++) dst[j] = __ldg(&p[(size_t)E + e[j]]);
    }

    uint4 hv[4];
#pragma unroll
    for (int j = 0; j < 4; j++)
        hv[j] = __ldg((const uint4*)(g_y + (size_t)src[j] * D_FEAT) + q);

#pragma unroll
    for (int j = 0; j < 4; j++) {
        if (!valid[j]) continue;
        __half* o = g_hout + (size_t)dst[j] * D_FEAT + (q << 3);
        asm volatile("red.global.add.noftz.v4.f16x2 [%0], {%1, %2, %3, %4};"
                     :: "l"(o), "r"(hv[j].x), "r"(hv[j].y), "r"(hv[j].z), "r"(hv[j].w)
                     : "memory");
    }
}

// ---------------------------------------------------------------------------
// Convert fp16 accumulator -> fp32 output. One thread per 8 halves.
// ---------------------------------------------------------------------------
__global__ __launch_bounds__(256) void convert_kernel(float* __restrict__ out, int n16) {
    int i = blockIdx.x * blockDim.x + threadIdx.x;
    if (i >= n16) return;
    uint4 h = ((const uint4*)g_hout)[i];
    float2 f0 = __half22float2(*(const __half2*)&h.x);
    float2 f1 = __half22float2(*(const __half2*)&h.y);
    float2 f2 = __half22float2(*(const __half2*)&h.z);
    float2 f3 = __half22float2(*(const __half2*)&h.w);
    float4* o = (float4*)out + (size_t)i * 2;
    o[0] = make_float4(f0.x, f0.y, f1.x, f1.y);
    o[1] = make_float4(f2.x, f2.y, f3.x, f3.y);
}

// ---------------------------------------------------------------------------
// Inputs: x [n*64 f32], edge_index [2*E int32/int64], W [64*64 f32], b [64].
// ---------------------------------------------------------------------------
extern "C" void kernel_launch(void* const* d_in, const int* in_sizes, int n_in,
                              void* d_out, int out_size) {
    const float* x   = (const float*)d_in[0];
    const void*  ei  = d_in[1];
    const float* W   = (const float*)d_in[2];
    const float* b   = (const float*)d_in[3];
    float*       out = (float*)d_out;

    int n = in_sizes[0] / D_FEAT;
    int E = in_sizes[1] / 2;
    int n16 = n * D_FEAT / 8;   // uint4 groups in the fp16 accumulator

    setup_kernel<<<(n16 + 255) / 256, 256>>>((const int*)ei, n16);

    mlp_kernel<<<(n + 63) / 64, 256>>>(x, W, b, n);

    int EQ = (E + 3) / 4;
    long long total = (long long)EQ * 8;
    int grid = (int)((total + 255) / 256);
    scatter_kernel<<<grid, 256>>>(ei, E, EQ);

    convert_kernel<<<(n16 + 255) / 256, 256>>>(out, n16);
}